// round 9
// baseline (speedup 1.0000x reference)
#include <cuda_runtime.h>
#include <cuda_bf16.h>

// NEP descriptor R8: 2-kernel self-cleaning pipeline.
//   scatter: inline dtype detect, compute (x|pair, ux, uy, uz) -> per-atom bins
//   gather: warp-role split (even warps: radial+vector, odd warps: quad),
//           resets g_count so the next graph replay starts from zeros.

#define NUM_TYPES 4
#define NR 11          // N_MAX_RADIAL+1 (= BASIS_RADIAL+1)
#define NA 7           // N_MAX_ANGULAR+1
#define BA 9           // BASIS_ANGULAR+1
#define MAX_ATOMS 50176
#define BIN 64         // slots per atom (Poisson(20) -> overflow ~1e-15)

__device__ int    g_count[MAX_ATOMS];      // zero-init at load; self-cleaned
__device__ float4 g_rec[MAX_ATOMS * BIN];  // (x|pair, ux, uy, uz)

__global__ __launch_bounds__(256)
void scatter_kernel(const void* __restrict__ edge_index,
                    const float* __restrict__ edge_length,
                    const float* __restrict__ edge_vec,
                    const void* __restrict__ types,
                    int E)
{
    int e = blockIdx.x * blockDim.x + threadIdx.x;
    if (e >= E) return;

    // dtype detect, uniform across all threads (L1-broadcast loads):
    // int64 indices < 2^31 seen as int32 pairs have zero odd words.
    const int* ei32 = (const int*)edge_index;
    bool idx64 = ((ei32[1] | ei32[3] | ei32[5] | ei32[7]) == 0);

    int row, col, ti, tj;
    if (idx64) {
        const long long* ei = (const long long*)edge_index;
        const long long* ty = (const long long*)types;
        row = (int)ei[e];
        col = (int)ei[E + e];
        ti = (int)ty[row]; tj = (int)ty[col];
    } else {
        const int* ei = (const int*)edge_index;
        const int* ty = (const int*)types;
        row = ei[e];
        col = ei[E + e];
        ti = ty[row]; tj = ty[col];
    }
    int pair = ti * NUM_TYPES + tj;

    float d = edge_length[e];
    float x = fmaf(d, 0.4f, -1.0f);        // 2*(d/5) - 1

    // pack pair into low 4 mantissa bits of x (<=16 ulp perturbation)
    int xb = (__float_as_int(x) & ~0xF) | pair;

    float vx = edge_vec[e * 3 + 0];
    float vy = edge_vec[e * 3 + 1];
    float vz = edge_vec[e * 3 + 2];
    float inv = 1.0f / fmaxf(d, 1e-8f);

    int slot = atomicAdd(&g_count[row], 1);
    int pos = row * BIN + min(slot, BIN - 1);   // clamp (never hit in practice)
    g_rec[pos] = make_float4(__int_as_float(xb), vx * inv, vy * inv, vz * inv);
}

// Block = 256 threads = 8 warps. Warp 2k (role A) and warp 2k+1 (role B)
// both cover atoms [blockIdx*128 + k*32 + lane]. A: radial + dipole vector
// (out[0..17]); B: quadrupole (out[18..24]). Roles are warp-uniform.
__global__ __launch_bounds__(256)
void gather_kernel(float* __restrict__ out,
                   const float* __restrict__ c_radial,
                   const float* __restrict__ c_angular,
                   int N)
{
    // Pair-minor shared tables: lanes differing only in pair hit distinct
    // banks (stride-1 within 16-word groups); same pair -> broadcast.
    __shared__ float crs[NR * NR * 16];   // [(b*11+n)*16 + pair]
    __shared__ float cas[BA * NA * 16];   // [(b*7+n)*16 + pair]

    for (int i = threadIdx.x; i < 16 * NR * NR; i += blockDim.x) {
        int pair = i / (NR * NR);
        int nb   = i % (NR * NR);
        int n = nb / NR, b = nb % NR;
        crs[(b * NR + n) * 16 + pair] = c_radial[i];
    }
    for (int i = threadIdx.x; i < 16 * NA * BA; i += blockDim.x) {
        int pair = i / (NA * BA);
        int nb   = i % (NA * BA);
        int n = nb / BA, b = nb % BA;
        cas[(b * NA + n) * 16 + pair] = c_angular[i];
    }
    __syncthreads();

    int wid  = threadIdx.x >> 5;
    int lane = threadIdx.x & 31;
    int roleB = wid & 1;
    int a = blockIdx.x * 128 + (wid >> 1) * 32 + lane;
    if (a >= N) return;

    int cnt = g_count[a];
    if (!roleB) g_count[a] = 0;           // self-clean for next replay
    int start = a * BIN;
    int end   = start + min(cnt, BIN);

    float* o = out + a * 25;

    float4 r;
    if (start < end) r = g_rec[start];

    if (!roleB) {
        // ---------------- role A: radial (separable) + dipole vector --------
        float Sr[NUM_TYPES * NR];         // Sr[t][b] = sum_{e: tj=t} cut*T_b
        float accV[NA * 3];
        #pragma unroll
        for (int k = 0; k < NUM_TYPES * NR; k++) Sr[k] = 0.0f;
        #pragma unroll
        for (int k = 0; k < NA * 3; k++) accV[k] = 0.0f;
        int ti4 = 0;

        for (int i = start; i < end; i++) {
            float4 r_n;
            if (i + 1 < end) r_n = g_rec[i + 1];

            int xb = __float_as_int(r.x);
            int pair = xb & 15;
            int tj = pair & 3;
            ti4 = pair & 12;
            float x = r.x;
            float ux = r.y, uy = r.z, uz = r.w;

            float s = fmaf(0.5f, x, 0.5f);
            float denom = fmaf(-s, s, 1.0f);
            float cut = (denom > 0.0f) ? __expf(1.0f - __fdividef(1.0f, denom)) : 0.0f;

            float T[NR];
            T[0] = cut;
            T[1] = x * cut;
            float x2 = 2.0f * x;
            #pragma unroll
            for (int k = 2; k < NR; k++) T[k] = fmaf(x2, T[k - 1], -T[k - 2]);

            #pragma unroll
            for (int t = 0; t < NUM_TYPES; t++) {
                float m = (tj == t) ? 1.0f : 0.0f;
                #pragma unroll
                for (int b = 0; b < NR; b++)
                    Sr[t * NR + b] = fmaf(m, T[b], Sr[t * NR + b]);
            }

            float af[NA];
            #pragma unroll
            for (int n = 0; n < NA; n++) {
                float acc = 0.0f;
                #pragma unroll
                for (int b = 0; b < BA; b++)
                    acc = fmaf(T[b], cas[(b * NA + n) * 16 + pair], acc);
                af[n] = acc;
            }

            #pragma unroll
            for (int n = 0; n < NA; n++) {
                float f = af[n];
                accV[n * 3 + 0] = fmaf(f, ux, accV[n * 3 + 0]);
                accV[n * 3 + 1] = fmaf(f, uy, accV[n * 3 + 1]);
                accV[n * 3 + 2] = fmaf(f, uz, accV[n * 3 + 2]);
            }
            r = r_n;
        }

        // radial finalize: o[n] = sum_t sum_b C[ti,t][n][b] * Sr[t][b]
        #pragma unroll
        for (int n = 0; n < NR; n++) {
            float acc = 0.0f;
            #pragma unroll
            for (int t = 0; t < NUM_TYPES; t++) {
                #pragma unroll
                for (int b = 0; b < NR; b++)
                    acc = fmaf(Sr[t * NR + b], crs[(b * NR + n) * 16 + ti4 + t], acc);
            }
            o[n] = acc;
        }
        #pragma unroll
        for (int n = 0; n < NA; n++) {
            float vx = accV[n * 3 + 0], vy = accV[n * 3 + 1], vz = accV[n * 3 + 2];
            o[11 + n] = vx * vx + vy * vy + vz * vz;
        }
    } else {
        // ---------------- role B: quadrupole tensor -------------------------
        float accQ[NA * 6];
        #pragma unroll
        for (int k = 0; k < NA * 6; k++) accQ[k] = 0.0f;

        for (int i = start; i < end; i++) {
            float4 r_n;
            if (i + 1 < end) r_n = g_rec[i + 1];

            int xb = __float_as_int(r.x);
            int pair = xb & 15;
            float x = r.x;
            float ux = r.y, uy = r.z, uz = r.w;

            float s = fmaf(0.5f, x, 0.5f);
            float denom = fmaf(-s, s, 1.0f);
            float cut = (denom > 0.0f) ? __expf(1.0f - __fdividef(1.0f, denom)) : 0.0f;

            float T[NR];
            T[0] = cut;
            T[1] = x * cut;
            float x2 = 2.0f * x;
            #pragma unroll
            for (int k = 2; k < BA; k++) T[k] = fmaf(x2, T[k - 1], -T[k - 2]);

            float af[NA];
            #pragma unroll
            for (int n = 0; n < NA; n++) {
                float acc = 0.0f;
                #pragma unroll
                for (int b = 0; b < BA; b++)
                    acc = fmaf(T[b], cas[(b * NA + n) * 16 + pair], acc);
                af[n] = acc;
            }

            float qxx = fmaf(1.5f * ux, ux, -0.5f);
            float qyy = fmaf(1.5f * uy, uy, -0.5f);
            float qzz = fmaf(1.5f * uz, uz, -0.5f);
            float qxy = 1.5f * ux * uy;
            float qxz = 1.5f * ux * uz;
            float qyz = 1.5f * uy * uz;

            #pragma unroll
            for (int n = 0; n < NA; n++) {
                float f = af[n];
                accQ[n * 6 + 0] = fmaf(f, qxx, accQ[n * 6 + 0]);
                accQ[n * 6 + 1] = fmaf(f, qyy, accQ[n * 6 + 1]);
                accQ[n * 6 + 2] = fmaf(f, qzz, accQ[n * 6 + 2]);
                accQ[n * 6 + 3] = fmaf(f, qxy, accQ[n * 6 + 3]);
                accQ[n * 6 + 4] = fmaf(f, qxz, accQ[n * 6 + 4]);
                accQ[n * 6 + 5] = fmaf(f, qyz, accQ[n * 6 + 5]);
            }
            r = r_n;
        }

        #pragma unroll
        for (int n = 0; n < NA; n++) {
            float xx = accQ[n * 6 + 0], yy = accQ[n * 6 + 1], zz = accQ[n * 6 + 2];
            float xy = accQ[n * 6 + 3], xz = accQ[n * 6 + 4], yz = accQ[n * 6 + 5];
            o[18 + n] = xx * xx + yy * yy + zz * zz
                      + 2.0f * (xy * xy + xz * xz + yz * yz);
        }
    }
}

extern "C" void kernel_launch(void* const* d_in, const int* in_sizes, int n_in,
                              void* d_out, int out_size)
{
    const void*  edge_index  = d_in[0];
    const float* edge_length = (const float*)d_in[1];
    const float* edge_vec    = (const float*)d_in[2];
    // d_in[3] = num_atoms scalar (unused; N derived from out_size)
    const void*  types       = d_in[4];
    const float* c_radial    = (const float*)d_in[5];
    const float* c_angular   = (const float*)d_in[6];

    int E = in_sizes[1];        // edge_length element count
    int N = out_size / 25;

    scatter_kernel<<<(E + 255) / 256, 256>>>(edge_index, edge_length, edge_vec,
                                             types, E);
    gather_kernel<<<(N + 127) / 128, 256>>>((float*)d_out, c_radial, c_angular, N);
}

// round 10
// speedup vs baseline: 1.0612x; 1.0612x over previous
#include <cuda_runtime.h>
#include <cuda_bf16.h>

// NEP descriptor R9: scatter -> gatherA (radial+vector) -> gatherB (quad).
// Temporal role split: separate kernels = separate register budgets =
// real occupancy gain (R8's in-kernel split kept the 220-reg union).

#define NUM_TYPES 4
#define NR 11          // N_MAX_RADIAL+1 (= BASIS_RADIAL+1)
#define NA 7           // N_MAX_ANGULAR+1
#define BA 9           // BASIS_ANGULAR+1
#define MAX_ATOMS 50176
#define BIN 64         // slots per atom (Poisson(20) -> overflow ~1e-15)

__device__ int    g_count[MAX_ATOMS];      // zero-init at load; self-cleaned by gatherB
__device__ float4 g_rec[MAX_ATOMS * BIN];  // (x|pair, ux, uy, uz)

__global__ __launch_bounds__(256)
void scatter_kernel(const void* __restrict__ edge_index,
                    const float* __restrict__ edge_length,
                    const float* __restrict__ edge_vec,
                    const void* __restrict__ types,
                    int E)
{
    int e = blockIdx.x * blockDim.x + threadIdx.x;
    if (e >= E) return;

    // dtype detect, uniform across threads (L1-broadcast loads):
    // int64 indices < 2^31 seen as int32 pairs have zero odd words.
    const int* ei32 = (const int*)edge_index;
    bool idx64 = ((ei32[1] | ei32[3] | ei32[5] | ei32[7]) == 0);

    int row, col, ti, tj;
    if (idx64) {
        const long long* ei = (const long long*)edge_index;
        const long long* ty = (const long long*)types;
        row = (int)ei[e];
        col = (int)ei[E + e];
        ti = (int)ty[row]; tj = (int)ty[col];
    } else {
        const int* ei = (const int*)edge_index;
        const int* ty = (const int*)types;
        row = ei[e];
        col = ei[E + e];
        ti = ty[row]; tj = ty[col];
    }
    int pair = ti * NUM_TYPES + tj;

    float d = edge_length[e];
    float x = fmaf(d, 0.4f, -1.0f);        // 2*(d/5) - 1

    // pack pair into low 4 mantissa bits of x (<=16 ulp perturbation)
    int xb = (__float_as_int(x) & ~0xF) | pair;

    float vx = edge_vec[e * 3 + 0];
    float vy = edge_vec[e * 3 + 1];
    float vz = edge_vec[e * 3 + 2];
    float inv = 1.0f / fmaxf(d, 1e-8f);

    int slot = atomicAdd(&g_count[row], 1);
    int pos = row * BIN + min(slot, BIN - 1);   // clamp (never hit in practice)
    g_rec[pos] = make_float4(__int_as_float(xb), vx * inv, vy * inv, vz * inv);
}

// Angular table layout for LDS.64: cas2[pair][n][10] (b padded 9->10).
// Lane address = pair*70 + n*10 + b words; 70 = 6 mod 32 -> 16 distinct pairs
// hit 16 distinct even banks; float2 loads span (even,odd) -> conflict-free.
__device__ __forceinline__ float af_dot(const float* cas2, int pair, int n,
                                        const float* T)
{
    const float* base = cas2 + pair * 70 + n * 10;
    const float2* cv = (const float2*)base;
    float acc = T[8] * base[8];
    #pragma unroll
    for (int j = 0; j < 4; j++) {
        float2 c2 = cv[j];
        acc = fmaf(T[2 * j], c2.x, acc);
        acc = fmaf(T[2 * j + 1], c2.y, acc);
    }
    return acc;
}

// ---------------- gatherA: radial (separable Sr) + dipole vector ------------
__global__ __launch_bounds__(128, 3)
void gatherA_kernel(float* __restrict__ out,
                    const float* __restrict__ c_radial,
                    const float* __restrict__ c_angular,
                    int N)
{
    __shared__ float crs[NR * NR * 16];   // [(b*11+n)*16 + pair], pair-minor
    __shared__ float cas2[16 * NA * 10];  // [pair][n][10]

    for (int i = threadIdx.x; i < 16 * NR * NR; i += blockDim.x) {
        int pair = i / (NR * NR);
        int nb   = i % (NR * NR);
        int n = nb / NR, b = nb % NR;
        crs[(b * NR + n) * 16 + pair] = c_radial[i];
    }
    for (int i = threadIdx.x; i < 16 * NA * BA; i += blockDim.x) {
        int pair = i / (NA * BA);
        int r    = i % (NA * BA);
        int n = r / BA, b = r % BA;
        cas2[pair * 70 + n * 10 + b] = c_angular[i];
    }
    __syncthreads();

    int a = blockIdx.x * blockDim.x + threadIdx.x;
    if (a >= N) return;

    int start = a * BIN;
    int end   = start + min(g_count[a], BIN);

    float Sr[NUM_TYPES * NR];             // Sr[t][b] = sum_{e: tj=t} cut*T_b
    float accV[NA * 3];
    #pragma unroll
    for (int k = 0; k < NUM_TYPES * NR; k++) Sr[k] = 0.0f;
    #pragma unroll
    for (int k = 0; k < NA * 3; k++) accV[k] = 0.0f;
    int ti4 = 0;

    float4 r;
    if (start < end) r = g_rec[start];

    for (int i = start; i < end; i++) {
        float4 r_n;
        if (i + 1 < end) r_n = g_rec[i + 1];

        int xb = __float_as_int(r.x);
        int pair = xb & 15;
        int tj = pair & 3;
        ti4 = pair & 12;
        float x = r.x;
        float ux = r.y, uy = r.z, uz = r.w;

        float s = fmaf(0.5f, x, 0.5f);
        float denom = fmaf(-s, s, 1.0f);
        float cut = (denom > 0.0f) ? __expf(1.0f - __fdividef(1.0f, denom)) : 0.0f;

        float T[NR];
        T[0] = cut;
        T[1] = x * cut;
        float x2 = 2.0f * x;
        #pragma unroll
        for (int k = 2; k < NR; k++) T[k] = fmaf(x2, T[k - 1], -T[k - 2]);

        #pragma unroll
        for (int t = 0; t < NUM_TYPES; t++) {
            float m = (tj == t) ? 1.0f : 0.0f;
            #pragma unroll
            for (int b = 0; b < NR; b++)
                Sr[t * NR + b] = fmaf(m, T[b], Sr[t * NR + b]);
        }

        #pragma unroll
        for (int n = 0; n < NA; n++) {
            float f = af_dot(cas2, pair, n, T);
            accV[n * 3 + 0] = fmaf(f, ux, accV[n * 3 + 0]);
            accV[n * 3 + 1] = fmaf(f, uy, accV[n * 3 + 1]);
            accV[n * 3 + 2] = fmaf(f, uz, accV[n * 3 + 2]);
        }
        r = r_n;
    }

    float* o = out + a * 25;

    // radial finalize: o[n] = sum_t sum_b C[ti,t][n][b] * Sr[t][b]
    #pragma unroll
    for (int n = 0; n < NR; n++) {
        float acc = 0.0f;
        #pragma unroll
        for (int t = 0; t < NUM_TYPES; t++) {
            #pragma unroll
            for (int b = 0; b < NR; b++)
                acc = fmaf(Sr[t * NR + b], crs[(b * NR + n) * 16 + ti4 + t], acc);
        }
        o[n] = acc;
    }
    #pragma unroll
    for (int n = 0; n < NA; n++) {
        float vx = accV[n * 3 + 0], vy = accV[n * 3 + 1], vz = accV[n * 3 + 2];
        o[11 + n] = vx * vx + vy * vy + vz * vz;
    }
}

// ---------------- gatherB: quadrupole tensor (+ self-clean) -----------------
__global__ __launch_bounds__(128, 4)
void gatherB_kernel(float* __restrict__ out,
                    const float* __restrict__ c_angular,
                    int N)
{
    __shared__ float cas2[16 * NA * 10];  // [pair][n][10]

    for (int i = threadIdx.x; i < 16 * NA * BA; i += blockDim.x) {
        int pair = i / (NA * BA);
        int r    = i % (NA * BA);
        int n = r / BA, b = r % BA;
        cas2[pair * 70 + n * 10 + b] = c_angular[i];
    }
    __syncthreads();

    int a = blockIdx.x * blockDim.x + threadIdx.x;
    if (a >= N) return;

    int cnt = g_count[a];
    g_count[a] = 0;                        // self-clean for next graph replay
    int start = a * BIN;
    int end   = start + min(cnt, BIN);

    float accQ[NA * 6];
    #pragma unroll
    for (int k = 0; k < NA * 6; k++) accQ[k] = 0.0f;

    float4 r;
    if (start < end) r = g_rec[start];

    for (int i = start; i < end; i++) {
        float4 r_n;
        if (i + 1 < end) r_n = g_rec[i + 1];

        int xb = __float_as_int(r.x);
        int pair = xb & 15;
        float x = r.x;
        float ux = r.y, uy = r.z, uz = r.w;

        float s = fmaf(0.5f, x, 0.5f);
        float denom = fmaf(-s, s, 1.0f);
        float cut = (denom > 0.0f) ? __expf(1.0f - __fdividef(1.0f, denom)) : 0.0f;

        float T[BA];
        T[0] = cut;
        T[1] = x * cut;
        float x2 = 2.0f * x;
        #pragma unroll
        for (int k = 2; k < BA; k++) T[k] = fmaf(x2, T[k - 1], -T[k - 2]);

        float qxx = fmaf(1.5f * ux, ux, -0.5f);
        float qyy = fmaf(1.5f * uy, uy, -0.5f);
        float qzz = fmaf(1.5f * uz, uz, -0.5f);
        float qxy = 1.5f * ux * uy;
        float qxz = 1.5f * ux * uz;
        float qyz = 1.5f * uy * uz;

        #pragma unroll
        for (int n = 0; n < NA; n++) {
            float f = af_dot(cas2, pair, n, T);
            accQ[n * 6 + 0] = fmaf(f, qxx, accQ[n * 6 + 0]);
            accQ[n * 6 + 1] = fmaf(f, qyy, accQ[n * 6 + 1]);
            accQ[n * 6 + 2] = fmaf(f, qzz, accQ[n * 6 + 2]);
            accQ[n * 6 + 3] = fmaf(f, qxy, accQ[n * 6 + 3]);
            accQ[n * 6 + 4] = fmaf(f, qxz, accQ[n * 6 + 4]);
            accQ[n * 6 + 5] = fmaf(f, qyz, accQ[n * 6 + 5]);
        }
        r = r_n;
    }

    float* o = out + a * 25;
    #pragma unroll
    for (int n = 0; n < NA; n++) {
        float xx = accQ[n * 6 + 0], yy = accQ[n * 6 + 1], zz = accQ[n * 6 + 2];
        float xy = accQ[n * 6 + 3], xz = accQ[n * 6 + 4], yz = accQ[n * 6 + 5];
        o[18 + n] = xx * xx + yy * yy + zz * zz
                  + 2.0f * (xy * xy + xz * xz + yz * yz);
    }
}

extern "C" void kernel_launch(void* const* d_in, const int* in_sizes, int n_in,
                              void* d_out, int out_size)
{
    const void*  edge_index  = d_in[0];
    const float* edge_length = (const float*)d_in[1];
    const float* edge_vec    = (const float*)d_in[2];
    // d_in[3] = num_atoms scalar (unused; N derived from out_size)
    const void*  types       = d_in[4];
    const float* c_radial    = (const float*)d_in[5];
    const float* c_angular   = (const float*)d_in[6];

    int E = in_sizes[1];        // edge_length element count
    int N = out_size / 25;

    scatter_kernel<<<(E + 255) / 256, 256>>>(edge_index, edge_length, edge_vec,
                                             types, E);
    gatherA_kernel<<<(N + 127) / 128, 128>>>((float*)d_out, c_radial, c_angular, N);
    gatherB_kernel<<<(N + 127) / 128, 128>>>((float*)d_out, c_angular, N);
}

// round 12
// speedup vs baseline: 1.4685x; 1.3838x over previous
#include <cuda_runtime.h>
#include <cuda_bf16.h>

// NEP descriptor R11 (= R10 resubmit after infra failure):
// types->int8 prepass, scatter, monolithic gather.
// - int8 type table (50KB) makes scatter's random type gathers L1-resident.
// - gather: R7 structure (separable radial Sr) + float2 LDS af_dot +
//   launch_bounds(128,3) for 12 warps/SM; self-cleans g_count.

#define NUM_TYPES 4
#define NR 11          // N_MAX_RADIAL+1 (= BASIS_RADIAL+1)
#define NA 7           // N_MAX_ANGULAR+1
#define BA 9           // BASIS_ANGULAR+1
#define MAX_ATOMS 50176
#define BIN 64         // slots per atom (Poisson(20) -> overflow ~1e-15)

__device__ int           g_count[MAX_ATOMS];      // zero at load; self-cleaned
__device__ unsigned char g_types[MAX_ATOMS];
__device__ float4        g_rec[MAX_ATOMS * BIN];  // (x|pair, ux, uy, uz)

// Convert types to int8 (dtype of types/edge_index detected from edge_index:
// int64 indices < 2^31 viewed as int32 pairs have all-zero odd words).
__global__ void types_kernel(const void* __restrict__ types,
                             const int* __restrict__ ei32, int N)
{
    int i = blockIdx.x * blockDim.x + threadIdx.x;
    if (i >= N) return;
    bool idx64 = ((ei32[1] | ei32[3] | ei32[5] | ei32[7]) == 0);
    int t = idx64 ? (int)((const long long*)types)[i]
                  : ((const int*)types)[i];
    g_types[i] = (unsigned char)t;
}

__global__ __launch_bounds__(256)
void scatter_kernel(const void* __restrict__ edge_index,
                    const float* __restrict__ edge_length,
                    const float* __restrict__ edge_vec,
                    int E)
{
    int e = blockIdx.x * blockDim.x + threadIdx.x;
    if (e >= E) return;

    const int* ei32 = (const int*)edge_index;
    bool idx64 = ((ei32[1] | ei32[3] | ei32[5] | ei32[7]) == 0);

    int row, col;
    if (idx64) {
        const long long* ei = (const long long*)edge_index;
        row = (int)ei[e];
        col = (int)ei[E + e];
    } else {
        row = ei32[e];
        col = ei32[E + e];
    }
    int ti = g_types[row];            // L1-resident 50KB table
    int tj = g_types[col];
    int pair = ti * NUM_TYPES + tj;

    float d = edge_length[e];
    float x = fmaf(d, 0.4f, -1.0f);   // 2*(d/5) - 1

    // pack pair into low 4 mantissa bits of x (<=16 ulp perturbation)
    int xb = (__float_as_int(x) & ~0xF) | pair;

    float vx = edge_vec[e * 3 + 0];
    float vy = edge_vec[e * 3 + 1];
    float vz = edge_vec[e * 3 + 2];
    float inv = 1.0f / fmaxf(d, 1e-8f);

    int slot = atomicAdd(&g_count[row], 1);
    int pos = row * BIN + min(slot, BIN - 1);   // clamp (never hit in practice)
    g_rec[pos] = make_float4(__int_as_float(xb), vx * inv, vy * inv, vz * inv);
}

// Angular table for LDS.64: cas2[pair][n][10] (b padded 9->10).
// Word address = pair*70 + n*10 + b; 70 = 6 mod 32 -> the 16 pairs map to 16
// distinct even banks; float2 spans (even,odd) -> conflict-free.
__device__ __forceinline__ float af_dot(const float* cas2, int pair, int n,
                                        const float* T)
{
    const float* base = cas2 + pair * 70 + n * 10;
    const float2* cv = (const float2*)base;
    float acc = T[8] * base[8];
    #pragma unroll
    for (int j = 0; j < 4; j++) {
        float2 c2 = cv[j];
        acc = fmaf(T[2 * j], c2.x, acc);
        acc = fmaf(T[2 * j + 1], c2.y, acc);
    }
    return acc;
}

__global__ __launch_bounds__(128, 3)
void gather_kernel(float* __restrict__ out,
                   const float* __restrict__ c_radial,
                   const float* __restrict__ c_angular,
                   int N)
{
    // crs pair-minor: [(b*11+n)*16 + pair] -> conflict-free / broadcast.
    __shared__ float crs[NR * NR * 16];
    __shared__ float cas2[16 * NA * 10];

    for (int i = threadIdx.x; i < 16 * NR * NR; i += blockDim.x) {
        int pair = i / (NR * NR);
        int nb   = i % (NR * NR);
        int n = nb / NR, b = nb % NR;
        crs[(b * NR + n) * 16 + pair] = c_radial[i];
    }
    for (int i = threadIdx.x; i < 16 * NA * BA; i += blockDim.x) {
        int pair = i / (NA * BA);
        int r    = i % (NA * BA);
        int n = r / BA, b = r % BA;
        cas2[pair * 70 + n * 10 + b] = c_angular[i];
    }
    __syncthreads();

    int a = blockIdx.x * blockDim.x + threadIdx.x;
    if (a >= N) return;

    int cnt = g_count[a];
    g_count[a] = 0;                    // self-clean for next graph replay
    int start = a * BIN;
    int end   = start + min(cnt, BIN);

    float Sr[NUM_TYPES * NR];          // Sr[t][b] = sum_{e: tj=t} cut*T_b
    float accV[NA * 3];
    float accQ[NA * 6];
    #pragma unroll
    for (int k = 0; k < NUM_TYPES * NR; k++) Sr[k] = 0.0f;
    #pragma unroll
    for (int k = 0; k < NA * 3; k++) accV[k] = 0.0f;
    #pragma unroll
    for (int k = 0; k < NA * 6; k++) accQ[k] = 0.0f;
    int ti4 = 0;

    float4 r;
    if (start < end) r = g_rec[start];

    for (int i = start; i < end; i++) {
        float4 r_n;
        if (i + 1 < end) r_n = g_rec[i + 1];

        int xb = __float_as_int(r.x);
        int pair = xb & 15;
        int tj = pair & 3;
        ti4 = pair & 12;
        float x = r.x;                 // pair bits kept: <=2e-6 rel perturb
        float ux = r.y, uy = r.z, uz = r.w;

        // envelope: s=(x+1)/2, cut=exp(1 - 1/(1-s^2))
        float s = fmaf(0.5f, x, 0.5f);
        float denom = fmaf(-s, s, 1.0f);
        float cut = (denom > 0.0f) ? __expf(1.0f - __fdividef(1.0f, denom)) : 0.0f;

        // cut-seeded Chebyshev: T[k] = cut * T_k(x)
        float T[NR];
        T[0] = cut;
        T[1] = x * cut;
        float x2 = 2.0f * x;
        #pragma unroll
        for (int k = 2; k < NR; k++) T[k] = fmaf(x2, T[k - 1], -T[k - 2]);

        // radial: predicated per-type basis sums (no LDS in edge loop)
        #pragma unroll
        for (int t = 0; t < NUM_TYPES; t++) {
            float m = (tj == t) ? 1.0f : 0.0f;
            #pragma unroll
            for (int b = 0; b < NR; b++)
                Sr[t * NR + b] = fmaf(m, T[b], Sr[t * NR + b]);
        }

        float qxx = fmaf(1.5f * ux, ux, -0.5f);
        float qyy = fmaf(1.5f * uy, uy, -0.5f);
        float qzz = fmaf(1.5f * uz, uz, -0.5f);
        float qxy = 1.5f * ux * uy;
        float qxz = 1.5f * ux * uz;
        float qyz = 1.5f * uy * uz;

        #pragma unroll
        for (int n = 0; n < NA; n++) {
            float f = af_dot(cas2, pair, n, T);
            accV[n * 3 + 0] = fmaf(f, ux, accV[n * 3 + 0]);
            accV[n * 3 + 1] = fmaf(f, uy, accV[n * 3 + 1]);
            accV[n * 3 + 2] = fmaf(f, uz, accV[n * 3 + 2]);
            accQ[n * 6 + 0] = fmaf(f, qxx, accQ[n * 6 + 0]);
            accQ[n * 6 + 1] = fmaf(f, qyy, accQ[n * 6 + 1]);
            accQ[n * 6 + 2] = fmaf(f, qzz, accQ[n * 6 + 2]);
            accQ[n * 6 + 3] = fmaf(f, qxy, accQ[n * 6 + 3]);
            accQ[n * 6 + 4] = fmaf(f, qxz, accQ[n * 6 + 4]);
            accQ[n * 6 + 5] = fmaf(f, qyz, accQ[n * 6 + 5]);
        }
        r = r_n;
    }

    float* o = out + a * 25;

    // radial finalize: o[n] = sum_t sum_b C[ti,t][n][b] * Sr[t][b]
    #pragma unroll
    for (int n = 0; n < NR; n++) {
        float acc = 0.0f;
        #pragma unroll
        for (int t = 0; t < NUM_TYPES; t++) {
            #pragma unroll
            for (int b = 0; b < NR; b++)
                acc = fmaf(Sr[t * NR + b], crs[(b * NR + n) * 16 + ti4 + t], acc);
        }
        o[n] = acc;
    }
    #pragma unroll
    for (int n = 0; n < NA; n++) {
        float vx = accV[n * 3 + 0], vy = accV[n * 3 + 1], vz = accV[n * 3 + 2];
        o[11 + n] = vx * vx + vy * vy + vz * vz;
    }
    #pragma unroll
    for (int n = 0; n < NA; n++) {
        float xx = accQ[n * 6 + 0], yy = accQ[n * 6 + 1], zz = accQ[n * 6 + 2];
        float xy = accQ[n * 6 + 3], xz = accQ[n * 6 + 4], yz = accQ[n * 6 + 5];
        o[18 + n] = xx * xx + yy * yy + zz * zz
                  + 2.0f * (xy * xy + xz * xz + yz * yz);
    }
}

extern "C" void kernel_launch(void* const* d_in, const int* in_sizes, int n_in,
                              void* d_out, int out_size)
{
    const void*  edge_index  = d_in[0];
    const float* edge_length = (const float*)d_in[1];
    const float* edge_vec    = (const float*)d_in[2];
    // d_in[3] = num_atoms scalar (unused; N derived from out_size)
    const void*  types       = d_in[4];
    const float* c_radial    = (const float*)d_in[5];
    const float* c_angular   = (const float*)d_in[6];

    int E = in_sizes[1];        // edge_length element count
    int N = out_size / 25;

    types_kernel<<<(N + 255) / 256, 256>>>(types, (const int*)edge_index, N);
    scatter_kernel<<<(E + 255) / 256, 256>>>(edge_index, edge_length, edge_vec, E);
    gather_kernel<<<(N + 127) / 128, 128>>>((float*)d_out, c_radial, c_angular, N);
}